// round 1
// baseline (speedup 1.0000x reference)
#include <cuda_runtime.h>
#include <cstdint>

#define NB 16
#define NT 2048
#define NV 512

// Scratch (allocation-free rule: __device__ globals).
// g_A holds L1 (B,T,V) first, then is reused for S (B,T,V).
// g_KT holds K transposed per batch: [b][u][s]  (V x T per batch).
__device__ float g_A[(size_t)NB * NT * NV];
__device__ float g_KT[(size_t)NB * NV * NT];

// ---------------------------------------------------------------------------
// Kernel 1: L1[b,s,v] = sum_{r<=s, idx[b,r]==v} pt[s-r]
// One block per (s, b). Scatter-add into a shared 512-float accumulator.
// ---------------------------------------------------------------------------
__global__ void k_build_l1(const int* __restrict__ idx,
                           const float* __restrict__ pt,
                           float* __restrict__ L1) {
    const int s = blockIdx.x, b = blockIdx.y;
    __shared__ float acc[NV];
    for (int v = threadIdx.x; v < NV; v += blockDim.x) acc[v] = 0.f;
    __syncthreads();
    const int* ib = idx + (size_t)b * NT;
    for (int r = threadIdx.x; r <= s; r += blockDim.x)
        atomicAdd(&acc[ib[r]], pt[s - r]);
    __syncthreads();
    float* out = L1 + ((size_t)b * NT + s) * NV;
    for (int v = threadIdx.x; v < NV; v += blockDim.x) out[v] = acc[v];
}

// ---------------------------------------------------------------------------
// Kernel 3: S[b,t,v] = sum_{s<=t, idx[b,s]==v} KT[b][idx[b,t]][s]
// One block per (t, b). KT row is contiguous in s -> coalesced reads.
// ---------------------------------------------------------------------------
__global__ void k_scatter_s(const int* __restrict__ idx,
                            const float* __restrict__ KT,
                            float* __restrict__ S) {
    const int t = blockIdx.x, b = blockIdx.y;
    __shared__ float acc[NV];
    for (int v = threadIdx.x; v < NV; v += blockDim.x) acc[v] = 0.f;
    __syncthreads();
    const int* ib = idx + (size_t)b * NT;
    const int q = ib[t];
    const float* krow = KT + ((size_t)b * NV + q) * NT;
    for (int s = threadIdx.x; s <= t; s += blockDim.x)
        atomicAdd(&acc[ib[s]], krow[s]);
    __syncthreads();
    float* out = S + ((size_t)b * NT + t) * NV;
    for (int v = threadIdx.x; v < NV; v += blockDim.x) out[v] = acc[v];
}

// ---------------------------------------------------------------------------
// tf32 GEMM: C[m,n] = sum_k A[m,k] * B[k,n], M = NB*NT, K = N = NV.
//   B_KN=true : Bsrc is row-major [k][n]   (Wq: K = L1 @ Wq)
//   B_KN=false: Bsrc is row-major [n][k]   (Wv: logits = S @ Wv^T)
//   TRANS_OUT=true : write C[m,n] to KT[b][n][s] with b=m/NT, s=m%NT
//   TRANS_OUT=false: write row-major C[m,n]
// Block tile 128x64, k-chunk 32, 256 threads (8 warps, 4x2 of 32x32),
// mma.sync.aligned.m16n8k8 tf32.
// ---------------------------------------------------------------------------
#define BM 128
#define BN 64
#define BK 32

__device__ __forceinline__ float to_tf32(float x) {
    float y;
    asm("cvt.rna.tf32.f32 %0, %1;" : "=f"(y) : "f"(x));
    return y;
}

template <bool B_KN, bool TRANS_OUT>
__global__ void __launch_bounds__(256, 2)
gemm_tf32(const float* __restrict__ A, const float* __restrict__ Bsrc,
          float* __restrict__ C) {
    __shared__ float As[BM][BK + 1];
    __shared__ float Bs[BN][BK + 1];

    const int m0 = blockIdx.y * BM;
    const int n0 = blockIdx.x * BN;
    const int tid = threadIdx.x;
    const int lane = tid & 31;
    const int warp = tid >> 5;
    const int wm = (warp & 3) * 32;   // warp offset in M within tile
    const int wn = (warp >> 2) * 32;  // warp offset in N within tile

    float c[2][4][4];
#pragma unroll
    for (int i = 0; i < 2; i++)
#pragma unroll
        for (int j = 0; j < 4; j++)
#pragma unroll
            for (int r = 0; r < 4; r++) c[i][j][r] = 0.f;

    for (int kt = 0; kt < NV; kt += BK) {
        // --- load A tile (128x32): 1024 float4, 4 per thread ---
#pragma unroll
        for (int i = 0; i < 4; i++) {
            int f4 = tid + i * 256;
            int r = f4 >> 3;
            int c4 = (f4 & 7) * 4;
            float4 v = *reinterpret_cast<const float4*>(
                &A[(size_t)(m0 + r) * NV + kt + c4]);
            As[r][c4 + 0] = to_tf32(v.x);
            As[r][c4 + 1] = to_tf32(v.y);
            As[r][c4 + 2] = to_tf32(v.z);
            As[r][c4 + 3] = to_tf32(v.w);
        }
        // --- load B tile into Bs[n][k] (col-major KxN for mma .col) ---
        if (B_KN) {
            // Bsrc[k][n], k rows of NV: transpose while loading
#pragma unroll
            for (int i = 0; i < 8; i++) {
                int e = tid + i * 256;       // 0..2047
                int k = e >> 6;
                int n = e & 63;
                Bs[n][k] = to_tf32(Bsrc[(size_t)(kt + k) * NV + n0 + n]);
            }
        } else {
            // Bsrc[n][k]: direct vectorized copy
#pragma unroll
            for (int i = 0; i < 2; i++) {
                int f4 = tid + i * 256;      // 0..511
                int n = f4 >> 3;
                int c4 = (f4 & 7) * 4;
                float4 v = *reinterpret_cast<const float4*>(
                    &Bsrc[(size_t)(n0 + n) * NV + kt + c4]);
                Bs[n][c4 + 0] = to_tf32(v.x);
                Bs[n][c4 + 1] = to_tf32(v.y);
                Bs[n][c4 + 2] = to_tf32(v.z);
                Bs[n][c4 + 3] = to_tf32(v.w);
            }
        }
        __syncthreads();

#pragma unroll
        for (int k8 = 0; k8 < BK; k8 += 8) {
            uint32_t a[2][4];
            uint32_t bf[4][2];
            const int kk = k8 + (lane & 3);
#pragma unroll
            for (int i = 0; i < 2; i++) {
                int r = wm + i * 16 + (lane >> 2);
                a[i][0] = __float_as_uint(As[r][kk]);
                a[i][1] = __float_as_uint(As[r + 8][kk]);
                a[i][2] = __float_as_uint(As[r][kk + 4]);
                a[i][3] = __float_as_uint(As[r + 8][kk + 4]);
            }
#pragma unroll
            for (int j = 0; j < 4; j++) {
                int n = wn + j * 8 + (lane >> 2);
                bf[j][0] = __float_as_uint(Bs[n][kk]);
                bf[j][1] = __float_as_uint(Bs[n][kk + 4]);
            }
#pragma unroll
            for (int i = 0; i < 2; i++)
#pragma unroll
                for (int j = 0; j < 4; j++)
                    asm volatile(
                        "mma.sync.aligned.m16n8k8.row.col.f32.tf32.tf32.f32 "
                        "{%0,%1,%2,%3}, {%4,%5,%6,%7}, {%8,%9}, {%0,%1,%2,%3};"
                        : "+f"(c[i][j][0]), "+f"(c[i][j][1]),
                          "+f"(c[i][j][2]), "+f"(c[i][j][3])
                        : "r"(a[i][0]), "r"(a[i][1]), "r"(a[i][2]), "r"(a[i][3]),
                          "r"(bf[j][0]), "r"(bf[j][1]));
        }
        __syncthreads();
    }

    // --- epilogue ---
#pragma unroll
    for (int i = 0; i < 2; i++)
#pragma unroll
        for (int j = 0; j < 4; j++)
#pragma unroll
            for (int r = 0; r < 4; r++) {
                int row = m0 + wm + i * 16 + (lane >> 2) + (r >> 1) * 8;
                int col = n0 + wn + j * 8 + 2 * (lane & 3) + (r & 1);
                if (TRANS_OUT) {
                    int b = row >> 11;          // /NT
                    int s = row & (NT - 1);
                    C[((size_t)(b * NV + col)) * NT + s] = c[i][j][r];
                } else {
                    C[(size_t)row * NV + col] = c[i][j][r];
                }
            }
}

// ---------------------------------------------------------------------------
extern "C" void kernel_launch(void* const* d_in, const int* in_sizes, int n_in,
                              void* d_out, int out_size) {
    const int* idx = (const int*)d_in[0];      // (B,T) int32
    const float* pt = (const float*)d_in[1];   // (T,1) f32
    const float* Wq = (const float*)d_in[2];   // (V,V) f32
    const float* Wv = (const float*)d_in[3];   // (V,V) f32
    float* out = (float*)d_out;                // (B,T,V) f32

    float *pA = nullptr, *pKT = nullptr;
    cudaGetSymbolAddress((void**)&pA, g_A);
    cudaGetSymbolAddress((void**)&pKT, g_KT);

    dim3 gridBT(NT, NB);
    dim3 gridGemm(NV / BN, (NB * NT) / BM);

    // 1) L1 = masked-Toeplitz scatter
    k_build_l1<<<gridBT, 256>>>(idx, pt, pA);
    // 2) K = L1 @ Wq, stored transposed per batch as KT[b][u][s]
    gemm_tf32<true, true><<<gridGemm, 256>>>(pA, Wq, pKT);
    // 3) S[b,t,v] = sum_{s<=t, idx_s=v} KT[b][idx_t][s]   (reuses g_A)
    k_scatter_s<<<gridBT, 256>>>(idx, pKT, pA);
    // 4) logits = S @ Wv^T
    gemm_tf32<false, false><<<gridGemm, 256>>>(pA, Wv, out);
}

// round 5
// speedup vs baseline: 2.1491x; 2.1491x over previous
#include <cuda_runtime.h>
#include <cstdint>

#define NB 16
#define NT 2048
#define NV 512
#define BM 128
#define BN 128
#define BK 32

// Scratch (allocation-free rule: __device__ globals).
__device__ float g_A[(size_t)NB * NT * NV];    // L1 then S (tf32-rounded)
__device__ float g_KT[(size_t)NB * NV * NT];   // K transposed per batch
__device__ float g_WqT[NV * NV];               // Wq transposed (tf32-rounded)
__device__ float g_WvR[NV * NV];               // Wv (tf32-rounded)

__device__ __forceinline__ float to_tf32(float x) {
    float y;
    asm("cvt.rna.tf32.f32 %0, %1;" : "=f"(y) : "f"(x));
    return y;
}

// ---------------------------------------------------------------------------
// Wq transpose (512x512) with tf32 RNA rounding on output
// ---------------------------------------------------------------------------
__global__ void k_transpose(const float* __restrict__ W, float* __restrict__ WT) {
    __shared__ float t[32][33];
    int x = blockIdx.x * 32 + threadIdx.x;
    int y = blockIdx.y * 32 + threadIdx.y;
#pragma unroll
    for (int j = 0; j < 32; j += 8)
        t[threadIdx.y + j][threadIdx.x] = W[(size_t)(y + j) * NV + x];
    __syncthreads();
    x = blockIdx.y * 32 + threadIdx.x;
    y = blockIdx.x * 32 + threadIdx.y;
#pragma unroll
    for (int j = 0; j < 32; j += 8)
        WT[(size_t)(y + j) * NV + x] = to_tf32(t[threadIdx.x][threadIdx.y + j]);
}

// ---------------------------------------------------------------------------
// Elementwise tf32 RNA rounding copy (for Wv)
// ---------------------------------------------------------------------------
__global__ void k_round(const float* __restrict__ src, float* __restrict__ dst) {
    int i = (blockIdx.x * 256 + threadIdx.x) * 4;
    float4 v = *(const float4*)(src + i);
    v.x = to_tf32(v.x); v.y = to_tf32(v.y);
    v.z = to_tf32(v.z); v.w = to_tf32(v.w);
    *(float4*)(dst + i) = v;
}

// ---------------------------------------------------------------------------
// Kernel 1: L1[b,s,v] = sum_{r<=s, idx[b,r]==v} pt[s-r]   (tf32-rounded out)
// ---------------------------------------------------------------------------
__global__ void k_build_l1(const int* __restrict__ idx,
                           const float* __restrict__ pt,
                           float* __restrict__ L1) {
    const int s = blockIdx.x, b = blockIdx.y;
    __shared__ float acc[NV];
    for (int v = threadIdx.x; v < NV; v += blockDim.x) acc[v] = 0.f;
    __syncthreads();
    const int* ib = idx + (size_t)b * NT;
    for (int r = threadIdx.x; r <= s; r += blockDim.x)
        atomicAdd(&acc[ib[r]], pt[s - r]);
    __syncthreads();
    float* out = L1 + ((size_t)b * NT + s) * NV;
    for (int v = threadIdx.x; v < NV; v += blockDim.x) out[v] = to_tf32(acc[v]);
}

// ---------------------------------------------------------------------------
// Kernel 3: S[b,t,v] = sum_{s<=t, idx[b,s]==v} KT[b][idx[b,t]][s]  (tf32 out)
// ---------------------------------------------------------------------------
__global__ void k_scatter_s(const int* __restrict__ idx,
                            const float* __restrict__ KT,
                            float* __restrict__ S) {
    const int t = blockIdx.x, b = blockIdx.y;
    __shared__ float acc[NV];
    for (int v = threadIdx.x; v < NV; v += blockDim.x) acc[v] = 0.f;
    __syncthreads();
    const int* ib = idx + (size_t)b * NT;
    const int q = ib[t];
    const float* krow = KT + ((size_t)b * NV + q) * NT;
    for (int s = threadIdx.x; s <= t; s += blockDim.x)
        atomicAdd(&acc[ib[s]], krow[s]);
    __syncthreads();
    float* out = S + ((size_t)b * NT + t) * NV;
    for (int v = threadIdx.x; v < NV; v += blockDim.x) out[v] = to_tf32(acc[v]);
}

// ---------------------------------------------------------------------------
// tf32 GEMM, CTA 128x128, BK=32, 8 warps of 64x32, XOR-swizzled smem,
// cp.async double-buffered. Operands are pre-rounded to tf32 (RNA) by
// producers, so raw byte copies are numerically safe.
// B is always row-major [n][k].
//   TRANS_OUT=true : write C[m,n] -> KT[b][n][s] via shared-staged transpose
// ---------------------------------------------------------------------------
__device__ __forceinline__ uint32_t smem_u32(const void* p) {
    return (uint32_t)__cvta_generic_to_shared(p);
}

template <bool TRANS_OUT>
__global__ void __launch_bounds__(256, 2)
gemm_tf32(const float* __restrict__ A, const float* __restrict__ Bsrc,
          float* __restrict__ C) {
    extern __shared__ __align__(16) float sm[];  // 16384 floats = 64KB
    float* Asm = sm;          // [2][128][32] swizzled
    float* Bsm = sm + 8192;   // [2][128][32] swizzled

    const int tid = threadIdx.x;
    const int lane = tid & 31, warp = tid >> 5;
    const int wm = (warp & 1) * 64, wn = (warp >> 1) * 32;
    const int q = lane >> 2, t4 = lane & 3;
    const int m0 = blockIdx.y * BM, n0 = blockIdx.x * BN;
    const int sw = q << 2;

    float c[4][4][4];
#pragma unroll
    for (int i = 0; i < 4; i++)
#pragma unroll
        for (int j = 0; j < 4; j++)
#pragma unroll
            for (int r = 0; r < 4; r++) c[i][j][r] = 0.f;

#define ISSUE_TILE(KT_, BUF_)                                                  \
    do {                                                                       \
        _Pragma("unroll") for (int i_ = 0; i_ < 4; i_++) {                     \
            int f4 = tid + i_ * 256;                                           \
            int m_ = f4 >> 3, k4 = f4 & 7;                                     \
            const float* src =                                                 \
                A + (size_t)(m0 + m_) * NV + (KT_) + k4 * 4;                   \
            uint32_t dst = smem_u32(                                           \
                &Asm[(BUF_)*4096 + m_ * 32 + ((k4 * 4) ^ ((m_ & 7) << 2))]);   \
            asm volatile("cp.async.cg.shared.global [%0], [%1], 16;" ::"r"(    \
                             dst),                                             \
                         "l"(src));                                            \
        }                                                                      \
        _Pragma("unroll") for (int i_ = 0; i_ < 4; i_++) {                     \
            int f4 = tid + i_ * 256;                                           \
            int n_ = f4 >> 3, k4 = f4 & 7;                                     \
            const float* src =                                                 \
                Bsrc + (size_t)(n0 + n_) * NV + (KT_) + k4 * 4;                \
            uint32_t dst = smem_u32(                                           \
                &Bsm[(BUF_)*4096 + n_ * 32 + ((k4 * 4) ^ ((n_ & 7) << 2))]);   \
            asm volatile("cp.async.cg.shared.global [%0], [%1], 16;" ::"r"(    \
                             dst),                                             \
                         "l"(src));                                            \
        }                                                                      \
        asm volatile("cp.async.commit_group;");                                \
    } while (0)

    ISSUE_TILE(0, 0);
    const int NKT = NV / BK;  // 16
    for (int it = 0; it < NKT; it++) {
        const int buf = it & 1;
        if (it + 1 < NKT) {
            ISSUE_TILE((it + 1) * BK, buf ^ 1);
            asm volatile("cp.async.wait_group 1;");
        } else {
            asm volatile("cp.async.wait_group 0;");
        }
        __syncthreads();

        const float* Ab = Asm + buf * 4096;
        const float* Bb = Bsm + buf * 4096;
#pragma unroll
        for (int k8 = 0; k8 < BK; k8 += 8) {
            const int c0 = (k8 | t4) ^ sw;
            const int c2 = c0 ^ 4;
            uint32_t a[4][4], bf[4][2];
#pragma unroll
            for (int i = 0; i < 4; i++) {
                const int row = (wm + i * 16 + q) * 32;
                a[i][0] = __float_as_uint(Ab[row + c0]);
                a[i][1] = __float_as_uint(Ab[row + 256 + c0]);
                a[i][2] = __float_as_uint(Ab[row + c2]);
                a[i][3] = __float_as_uint(Ab[row + 256 + c2]);
            }
#pragma unroll
            for (int j = 0; j < 4; j++) {
                const int row = (wn + j * 8 + q) * 32;
                bf[j][0] = __float_as_uint(Bb[row + c0]);
                bf[j][1] = __float_as_uint(Bb[row + c2]);
            }
#pragma unroll
            for (int i = 0; i < 4; i++)
#pragma unroll
                for (int j = 0; j < 4; j++)
                    asm volatile(
                        "mma.sync.aligned.m16n8k8.row.col.f32.tf32.tf32.f32 "
                        "{%0,%1,%2,%3}, {%4,%5,%6,%7}, {%8,%9}, {%0,%1,%2,%3};"
                        : "+f"(c[i][j][0]), "+f"(c[i][j][1]),
                          "+f"(c[i][j][2]), "+f"(c[i][j][3])
                        : "r"(a[i][0]), "r"(a[i][1]), "r"(a[i][2]),
                          "r"(a[i][3]), "r"(bf[j][0]), "r"(bf[j][1]));
        }
        __syncthreads();
    }
#undef ISSUE_TILE

    if (TRANS_OUT) {
        // C[m,n] -> KT[b][n][s], staged through shared for coalesced stores
        const int b = m0 >> 11;          // / NT
        const int s0 = m0 & (NT - 1);
        float* stg = sm;                 // [64][136] = 8704 floats
#pragma unroll
        for (int p = 0; p < 2; p++) {
            __syncthreads();
            if ((warp >> 2) == p) {
#pragma unroll
                for (int i = 0; i < 4; i++)
#pragma unroll
                    for (int j = 0; j < 4; j++)
#pragma unroll
                        for (int r = 0; r < 4; r++) {
                            int row = wm + i * 16 + q + (r >> 1) * 8;
                            int col = wn + j * 8 + 2 * t4 + (r & 1) - p * 64;
                            stg[col * 136 + row] = c[i][j][r];
                        }
            }
            __syncthreads();
            const int nn = tid >> 2, ch = tid & 3;
            float* dst = C + ((size_t)(b * NV + n0 + p * 64 + nn)) * NT + s0;
            const float* srow = stg + nn * 136;
#pragma unroll
            for (int w = 0; w < 8; w++) {
                int f = ch * 32 + w * 4;
                *(float4*)(dst + f) = *(const float4*)(srow + f);
            }
        }
    } else {
        float* Cb = C + (size_t)m0 * NV + n0;
#pragma unroll
        for (int i = 0; i < 4; i++)
#pragma unroll
            for (int j = 0; j < 4; j++) {
                const int row = wm + i * 16 + q;
                const int col = wn + j * 8 + 2 * t4;
                float2 v0 = make_float2(c[i][j][0], c[i][j][1]);
                float2 v1 = make_float2(c[i][j][2], c[i][j][3]);
                *(float2*)&Cb[(size_t)row * NV + col] = v0;
                *(float2*)&Cb[(size_t)(row + 8) * NV + col] = v1;
            }
    }
}

// ---------------------------------------------------------------------------
extern "C" void kernel_launch(void* const* d_in, const int* in_sizes, int n_in,
                              void* d_out, int out_size) {
    const int* idx = (const int*)d_in[0];     // (B,T) int32
    const float* pt = (const float*)d_in[1];  // (T,1) f32
    const float* Wq = (const float*)d_in[2];  // (V,V) f32
    const float* Wv = (const float*)d_in[3];  // (V,V) f32
    float* out = (float*)d_out;               // (B,T,V) f32

    float *pA = nullptr, *pKT = nullptr, *pWqT = nullptr, *pWvR = nullptr;
    cudaGetSymbolAddress((void**)&pA, g_A);
    cudaGetSymbolAddress((void**)&pKT, g_KT);
    cudaGetSymbolAddress((void**)&pWqT, g_WqT);
    cudaGetSymbolAddress((void**)&pWvR, g_WvR);

    cudaFuncSetAttribute(gemm_tf32<true>,
                         cudaFuncAttributeMaxDynamicSharedMemorySize, 65536);
    cudaFuncSetAttribute(gemm_tf32<false>,
                         cudaFuncAttributeMaxDynamicSharedMemorySize, 65536);

    dim3 gridBT(NT, NB);
    dim3 gridGemm(NV / BN, (NB * NT) / BM);

    // 0) WqT = round_tf32(Wq^T);  WvR = round_tf32(Wv)
    k_transpose<<<dim3(16, 16), dim3(32, 8)>>>(Wq, pWqT);
    k_round<<<(NV * NV) / 1024, 256>>>(Wv, pWvR);
    // 1) L1 = masked-Toeplitz scatter (tf32-rounded)
    k_build_l1<<<gridBT, 256>>>(idx, pt, pA);
    // 2) K = L1 @ Wq, stored transposed per batch as KT[b][u][s]
    gemm_tf32<true><<<gridGemm, 256, 65536>>>(pA, pWqT, pKT);
    // 3) S[b,t,v] = sum_{s<=t, idx_s=v} KT[b][idx_t][s]   (reuses g_A)
    k_scatter_s<<<gridBT, 256>>>(idx, pKT, pA);
    // 4) logits = S @ Wv^T
    gemm_tf32<false><<<gridGemm, 256, 65536>>>(pA, pWvR, out);
}